// round 1
// baseline (speedup 1.0000x reference)
#include <cuda_runtime.h>
#include <math.h>
#include <math_constants.h>

// Problem constants
#define Bb 2
#define Ls 2048
#define Hh 16
#define Ee 64
#define BQ 64
#define BK 64
#define SCALE_LOG2E (0.125f * 1.4426950408889634f)

// Q/K/V layout: [B, L, H, E]  -> ((b*L + l)*H + h)*E + e   (row stride H*E = 1024 floats)
// A   layout:   [B, H, L, S]  -> ((b*H + h)*L + l)*L + s
// O   layout:   [B, L, H, E]

__global__ __launch_bounds__(256)
void attn_fused(const float* __restrict__ Q, const float* __restrict__ K,
                const float* __restrict__ V, float* __restrict__ O,
                float* __restrict__ A)
{
    __shared__ __align__(16) float QsT[Ee][BQ];   // Q^T tile: [e][r], scale folded in
    __shared__ __align__(16) float KP [Ee][BK];   // K^T tile [e][c]; reused as P^T [c][r]
    __shared__ __align__(16) float Vs [BK][Ee];   // V tile row-major [c][e]

    const int mt  = blockIdx.x;
    const int h   = blockIdx.y;
    const int b   = blockIdx.z;
    const int tid = threadIdx.x;
    const int tx  = tid & 15;       // score-col group
    const int ty  = tid >> 4;       // score-row group
    const int m0  = mt * BQ;
    const int ntiles = mt + 1;

    const float* Qbase = Q + (((size_t)b * Ls + m0) * Hh + h) * Ee;
    const float* Kb0   = K + (((size_t)b * Ls) * Hh + h) * Ee;
    const float* Vb0   = V + (((size_t)b * Ls) * Hh + h) * Ee;
    float* Abase       = A + (((size_t)b * Hh + h) * Ls + m0) * (size_t)Ls;

    // ---- load Q tile transposed, folding scale*log2(e) ----
    #pragma unroll
    for (int k = 0; k < 4; k++) {
        int c = tid + k * 256;
        int r = c >> 4, e4 = c & 15;
        float4 v = *(const float4*)(Qbase + (size_t)r * (Hh * Ee) + e4 * 4);
        QsT[e4 * 4 + 0][r] = v.x * SCALE_LOG2E;
        QsT[e4 * 4 + 1][r] = v.y * SCALE_LOG2E;
        QsT[e4 * 4 + 2][r] = v.z * SCALE_LOG2E;
        QsT[e4 * 4 + 3][r] = v.w * SCALE_LOG2E;
    }

    // ---- zero-fill fully masked portion of A rows (cols >= ntiles*BK) ----
    {
        int c0     = ntiles * BK;
        int width4 = (Ls - c0) >> 2;
        int tot    = BQ * width4;
        for (int idx = tid; idx < tot; idx += 256) {
            int r  = idx / width4;
            int c4 = idx - r * width4;
            *(float4*)(Abase + (size_t)r * Ls + c0 + c4 * 4) = make_float4(0.f, 0.f, 0.f, 0.f);
        }
    }

    // per-thread row stats (rows 4*ty+i), replicated across the 16 lanes of each row group
    float mreg[4], zreg[4];
    #pragma unroll
    for (int i = 0; i < 4; i++) { mreg[i] = -CUDART_INF_F; zreg[i] = 0.f; }

    __syncthreads();

    // ================= pass 1: compute per-row max and denominator =================
    for (int nt = 0; nt < ntiles; nt++) {
        const int n0 = nt * BK;
        const float* Kbase = Kb0 + (size_t)n0 * (Hh * Ee);
        #pragma unroll
        for (int k = 0; k < 4; k++) {
            int c = tid + k * 256;
            int r = c >> 4, e4 = c & 15;
            float4 v = *(const float4*)(Kbase + (size_t)r * (Hh * Ee) + e4 * 4);
            KP[e4 * 4 + 0][r] = v.x;
            KP[e4 * 4 + 1][r] = v.y;
            KP[e4 * 4 + 2][r] = v.z;
            KP[e4 * 4 + 3][r] = v.w;
        }
        __syncthreads();

        float acc[4][4];
        #pragma unroll
        for (int i = 0; i < 4; i++)
            #pragma unroll
            for (int j = 0; j < 4; j++) acc[i][j] = 0.f;

        #pragma unroll 8
        for (int e = 0; e < Ee; e++) {
            float4 a4 = *(const float4*)&QsT[e][ty * 4];
            float4 b4 = *(const float4*)&KP[e][tx * 4];
            float av[4] = {a4.x, a4.y, a4.z, a4.w};
            float bv[4] = {b4.x, b4.y, b4.z, b4.w};
            #pragma unroll
            for (int i = 0; i < 4; i++)
                #pragma unroll
                for (int j = 0; j < 4; j++) acc[i][j] = fmaf(av[i], bv[j], acc[i][j]);
        }

        if (nt == mt) {
            #pragma unroll
            for (int i = 0; i < 4; i++)
                #pragma unroll
                for (int j = 0; j < 4; j++)
                    if (tx * 4 + j > ty * 4 + i) acc[i][j] = -CUDART_INF_F;
        }

        #pragma unroll
        for (int i = 0; i < 4; i++) {
            float tmax = fmaxf(fmaxf(acc[i][0], acc[i][1]), fmaxf(acc[i][2], acc[i][3]));
            #pragma unroll
            for (int o = 8; o >= 1; o >>= 1)
                tmax = fmaxf(tmax, __shfl_xor_sync(0xffffffffu, tmax, o, 16));
            float mnew = fmaxf(mreg[i], tmax);
            float s = exp2f(acc[i][0] - mnew) + exp2f(acc[i][1] - mnew)
                    + exp2f(acc[i][2] - mnew) + exp2f(acc[i][3] - mnew);
            #pragma unroll
            for (int o = 8; o >= 1; o >>= 1)
                s += __shfl_xor_sync(0xffffffffu, s, o, 16);
            zreg[i] = zreg[i] * exp2f(mreg[i] - mnew) + s;
            mreg[i] = mnew;
        }
        __syncthreads();   // all KP reads done before next tile load
    }

    float zinv[4];
    #pragma unroll
    for (int i = 0; i < 4; i++) zinv[i] = 1.0f / zreg[i];

    float oacc[4][4];
    #pragma unroll
    for (int i = 0; i < 4; i++)
        #pragma unroll
        for (int j = 0; j < 4; j++) oacc[i][j] = 0.f;

    // ================= pass 2: recompute scores, write A, accumulate O =================
    for (int nt = 0; nt < ntiles; nt++) {
        const int n0 = nt * BK;
        const float* Kbase = Kb0 + (size_t)n0 * (Hh * Ee);
        const float* Vbase = Vb0 + (size_t)n0 * (Hh * Ee);
        #pragma unroll
        for (int k = 0; k < 4; k++) {
            int c = tid + k * 256;
            int r = c >> 4, e4 = c & 15;
            float4 kv = *(const float4*)(Kbase + (size_t)r * (Hh * Ee) + e4 * 4);
            KP[e4 * 4 + 0][r] = kv.x;
            KP[e4 * 4 + 1][r] = kv.y;
            KP[e4 * 4 + 2][r] = kv.z;
            KP[e4 * 4 + 3][r] = kv.w;
            float4 vv = *(const float4*)(Vbase + (size_t)r * (Hh * Ee) + e4 * 4);
            *(float4*)&Vs[r][e4 * 4] = vv;
        }
        __syncthreads();

        float acc[4][4];
        #pragma unroll
        for (int i = 0; i < 4; i++)
            #pragma unroll
            for (int j = 0; j < 4; j++) acc[i][j] = 0.f;

        #pragma unroll 8
        for (int e = 0; e < Ee; e++) {
            float4 a4 = *(const float4*)&QsT[e][ty * 4];
            float4 b4 = *(const float4*)&KP[e][tx * 4];
            float av[4] = {a4.x, a4.y, a4.z, a4.w};
            float bv[4] = {b4.x, b4.y, b4.z, b4.w};
            #pragma unroll
            for (int i = 0; i < 4; i++)
                #pragma unroll
                for (int j = 0; j < 4; j++) acc[i][j] = fmaf(av[i], bv[j], acc[i][j]);
        }

        if (nt == mt) {
            #pragma unroll
            for (int i = 0; i < 4; i++)
                #pragma unroll
                for (int j = 0; j < 4; j++)
                    if (tx * 4 + j > ty * 4 + i) acc[i][j] = -CUDART_INF_F;
        }

        __syncthreads();   // all score reads of KP done before overwriting with P^T

        #pragma unroll
        for (int i = 0; i < 4; i++) {
            #pragma unroll
            for (int j = 0; j < 4; j++) {
                float p = exp2f(acc[i][j] - mreg[i]) * zinv[i];
                KP[tx * 4 + j][ty * 4 + i] = p;     // P^T: [c][r]
            }
        }
        __syncthreads();

        // coalesced A write from staged P^T
        {
            int rA = tid >> 2;        // 0..63
            int q  = tid & 3;         // 16-col quarter
            float* Arow = Abase + (size_t)rA * Ls + n0 + q * 16;
            #pragma unroll
            for (int jj = 0; jj < 16; jj += 4) {
                float4 w;
                w.x = KP[q * 16 + jj + 0][rA];
                w.y = KP[q * 16 + jj + 1][rA];
                w.z = KP[q * 16 + jj + 2][rA];
                w.w = KP[q * 16 + jj + 3][rA];
                *(float4*)(Arow + jj) = w;
            }
        }

        // O += P * V : rows 4*ty+i (query rows), cols 4*tx+j (E dim)
        #pragma unroll 8
        for (int c = 0; c < BK; c++) {
            float4 p4 = *(const float4*)&KP[c][ty * 4];
            float4 v4 = *(const float4*)&Vs[c][tx * 4];
            float pv[4] = {p4.x, p4.y, p4.z, p4.w};
            float vv[4] = {v4.x, v4.y, v4.z, v4.w};
            #pragma unroll
            for (int i = 0; i < 4; i++)
                #pragma unroll
                for (int j = 0; j < 4; j++) oacc[i][j] = fmaf(pv[i], vv[j], oacc[i][j]);
        }
        __syncthreads();   // KP/Vs consumed before next tile load
    }

    // ---- write O tile ----
    float* Ob = O + (((size_t)b * Ls + m0) * Hh + h) * Ee;
    #pragma unroll
    for (int i = 0; i < 4; i++) {
        float4 w = make_float4(oacc[i][0], oacc[i][1], oacc[i][2], oacc[i][3]);
        *(float4*)(Ob + (size_t)(ty * 4 + i) * (Hh * Ee) + tx * 4) = w;
    }
}

extern "C" void kernel_launch(void* const* d_in, const int* in_sizes, int n_in,
                              void* d_out, int out_size) {
    const float* Q = (const float*)d_in[0];
    const float* K = (const float*)d_in[1];
    const float* V = (const float*)d_in[2];
    float* O = (float*)d_out;
    float* A = (float*)d_out + (size_t)Bb * Ls * Hh * Ee;   // tuple order: (V, A)

    dim3 grid(Ls / BQ, Hh, Bb);
    attn_fused<<<grid, 256>>>(Q, K, V, O, A);
}

// round 3
// speedup vs baseline: 1.9452x; 1.9452x over previous
#include <cuda_runtime.h>
#include <math.h>

#define Bb 2
#define Ls 2048
#define Hh 16
#define Ee 64
#define BQ 128
#define BK 64
#define SCALE_LOG2E (0.125f * 1.4426950408889634f)
#define QW 132
#define KW 68
#define VW 68
#define PW 132
#define SMEM_FLOATS (64*QW + 64*KW + 64*VW + 64*PW)   // 25600 floats = 100 KB

__device__ float g_Zinv[Bb * Hh * Ls];

// Q/K/V layout: [B, L, H, E] -> ((b*L + l)*H + h)*E + e   (row stride H*E = 1024)
// A layout:     [B, H, L, S]
// O layout:     [B, L, H, E]

__global__ __launch_bounds__(256, 2)
void attn1(const float* __restrict__ Q, const float* __restrict__ K,
           const float* __restrict__ V, float* __restrict__ O,
           float* __restrict__ A)
{
    extern __shared__ float sm[];
    float* QsT = sm;                       // [64][QW]  Q^T, scale folded
    float* Ks  = sm + 64 * QW;             // [64][KW]  K^T tile
    float* Vs  = Ks + 64 * KW;             // [64][VW]  V tile row-major
    float* PT  = Vs + 64 * VW;             // [64][PW]  P~^T tile

    const int h   = blockIdx.y;
    const int b   = blockIdx.z;
    const int tid = threadIdx.x;
    const int tx  = tid & 15;
    const int ty  = tid >> 4;
    const int bh  = b * Hh + h;

    const float* Kb0 = K + ((size_t)b * Ls * Hh + h) * Ee;
    const float* Vb0 = V + ((size_t)b * Ls * Hh + h) * Ee;

    // two row-tiles per block for load balance: mt and 15-mt (36 K-tiles total)
    #pragma unroll 1
    for (int half = 0; half < 2; half++) {
        const int mt = half ? (Ls / BQ - 1) - blockIdx.x : blockIdx.x;
        const int m0 = mt * BQ;

        const float* Qbase = Q + (((size_t)b * Ls + m0) * Hh + h) * Ee;
        float* Abase       = A + ((size_t)bh * Ls + m0) * (size_t)Ls;

        __syncthreads();   // previous half's smem reads done

        // ---- load Q tile transposed, folding scale*log2(e) ----
        #pragma unroll
        for (int p = 0; p < 8; p++) {
            int r = ty + p * 16;
            float4 v = *(const float4*)(Qbase + (size_t)r * (Hh * Ee) + tx * 4);
            QsT[(tx * 4 + 0) * QW + r] = v.x * SCALE_LOG2E;
            QsT[(tx * 4 + 1) * QW + r] = v.y * SCALE_LOG2E;
            QsT[(tx * 4 + 2) * QW + r] = v.z * SCALE_LOG2E;
            QsT[(tx * 4 + 3) * QW + r] = v.w * SCALE_LOG2E;
        }

        // ---- zero-fill fully masked A columns [m0+BQ, Ls) ----
        if (m0 + BQ < Ls) {
            int c0  = m0 + BQ;
            int w4  = (Ls - c0) >> 2;
            int tot = BQ * w4;
            for (int idx = tid; idx < tot; idx += 256) {
                int r  = idx / w4;
                int c4 = idx - r * w4;
                *(float4*)(Abase + (size_t)r * Ls + c0 + c4 * 4) =
                    make_float4(0.f, 0.f, 0.f, 0.f);
            }
        }

        float oacc[8][4];
        float zp[8];
        #pragma unroll
        for (int i = 0; i < 8; i++) {
            zp[i] = 0.f;
            #pragma unroll
            for (int j = 0; j < 4; j++) oacc[i][j] = 0.f;
        }

        __syncthreads();

        const int ntiles = 2 * mt + 2;
        for (int nt = 0; nt < ntiles; nt++) {
            const int n0 = nt * BK;
            const float* Kbase = Kb0 + (size_t)n0 * (Hh * Ee);
            const float* Vbase = Vb0 + (size_t)n0 * (Hh * Ee);

            // load K (transposed) and V (row-major)
            #pragma unroll
            for (int p = 0; p < 4; p++) {
                int c = ty + p * 16;
                float4 kv = *(const float4*)(Kbase + (size_t)c * (Hh * Ee) + tx * 4);
                Ks[(tx * 4 + 0) * KW + c] = kv.x;
                Ks[(tx * 4 + 1) * KW + c] = kv.y;
                Ks[(tx * 4 + 2) * KW + c] = kv.z;
                Ks[(tx * 4 + 3) * KW + c] = kv.w;
                *(float4*)(Vs + c * VW + tx * 4) =
                    *(const float4*)(Vbase + (size_t)c * (Hh * Ee) + tx * 4);
            }
            __syncthreads();

            // ---- S = Q K^T (scaled, in log2 domain) ----
            float acc[8][4];
            #pragma unroll
            for (int i = 0; i < 8; i++)
                #pragma unroll
                for (int j = 0; j < 4; j++) acc[i][j] = 0.f;

            #pragma unroll 8
            for (int e = 0; e < Ee; e++) {
                float4 a0 = *(const float4*)&QsT[e * QW + ty * 8];
                float4 a1 = *(const float4*)&QsT[e * QW + ty * 8 + 4];
                float4 bv = *(const float4*)&Ks[e * KW + tx * 4];
                float av[8] = {a0.x, a0.y, a0.z, a0.w, a1.x, a1.y, a1.z, a1.w};
                float bb[4] = {bv.x, bv.y, bv.z, bv.w};
                #pragma unroll
                for (int i = 0; i < 8; i++)
                    #pragma unroll
                    for (int j = 0; j < 4; j++)
                        acc[i][j] = fmaf(av[i], bb[j], acc[i][j]);
            }

            // ---- P~ = exp2(S) with causal mask; accumulate Z partials ----
            if (nt >= 2 * mt) {
                #pragma unroll
                for (int i = 0; i < 8; i++)
                    #pragma unroll
                    for (int j = 0; j < 4; j++) {
                        int col = n0 + tx * 4 + j;
                        int row = m0 + ty * 8 + i;
                        acc[i][j] = (col <= row) ? exp2f(acc[i][j]) : 0.f;
                    }
            } else {
                #pragma unroll
                for (int i = 0; i < 8; i++)
                    #pragma unroll
                    for (int j = 0; j < 4; j++)
                        acc[i][j] = exp2f(acc[i][j]);
            }
            #pragma unroll
            for (int i = 0; i < 8; i++)
                zp[i] += (acc[i][0] + acc[i][1]) + (acc[i][2] + acc[i][3]);

            // ---- write unnormalized P~ to A (registers -> global, coalesced) ----
            #pragma unroll
            for (int i = 0; i < 8; i++)
                *(float4*)(Abase + (size_t)(ty * 8 + i) * Ls + n0 + tx * 4) =
                    make_float4(acc[i][0], acc[i][1], acc[i][2], acc[i][3]);

            // ---- stage P~^T into smem for the PV GEMM ----
            #pragma unroll
            for (int j = 0; j < 4; j++) {
                *(float4*)&PT[(tx * 4 + j) * PW + ty * 8] =
                    make_float4(acc[0][j], acc[1][j], acc[2][j], acc[3][j]);
                *(float4*)&PT[(tx * 4 + j) * PW + ty * 8 + 4] =
                    make_float4(acc[4][j], acc[5][j], acc[6][j], acc[7][j]);
            }
            __syncthreads();

            // ---- O += P~ V ----
            #pragma unroll 8
            for (int c = 0; c < BK; c++) {
                float4 p0 = *(const float4*)&PT[c * PW + ty * 8];
                float4 p1 = *(const float4*)&PT[c * PW + ty * 8 + 4];
                float4 vv = *(const float4*)&Vs[c * VW + tx * 4];
                float pv[8] = {p0.x, p0.y, p0.z, p0.w, p1.x, p1.y, p1.z, p1.w};
                float vb[4] = {vv.x, vv.y, vv.z, vv.w};
                #pragma unroll
                for (int i = 0; i < 8; i++)
                    #pragma unroll
                    for (int j = 0; j < 4; j++)
                        oacc[i][j] = fmaf(pv[i], vb[j], oacc[i][j]);
            }
            __syncthreads();
        }

        // ---- finalize: Z reduce, scale O, store O + Zinv ----
        #pragma unroll
        for (int i = 0; i < 8; i++) {
            float z = zp[i];
            #pragma unroll
            for (int o = 8; o >= 1; o >>= 1)
                z += __shfl_xor_sync(0xffffffffu, z, o, 16);
            float zi = 1.0f / z;
            int row = m0 + ty * 8 + i;
            if (tx == 0) g_Zinv[bh * Ls + row] = zi;
            float4 w = make_float4(oacc[i][0] * zi, oacc[i][1] * zi,
                                   oacc[i][2] * zi, oacc[i][3] * zi);
            *(float4*)(O + (((size_t)b * Ls + row) * Hh + h) * Ee + tx * 4) = w;
        }
    }
}

// normalize the lower-triangular region of A by 1/Z
__global__ __launch_bounds__(256)
void normA(float* __restrict__ A)
{
    int row = blockIdx.x;                      // (b*H + h)*L + r
    int r   = row & (Ls - 1);
    int n4  = (((r >> 7) + 1) << 7) >> 2;      // float4 count to scale
    float zi = g_Zinv[row];
    float4* p = (float4*)(A + (size_t)row * Ls);
    for (int i = threadIdx.x; i < n4; i += 256) {
        float4 v = p[i];
        v.x *= zi; v.y *= zi; v.z *= zi; v.w *= zi;
        p[i] = v;
    }
}

extern "C" void kernel_launch(void* const* d_in, const int* in_sizes, int n_in,
                              void* d_out, int out_size) {
    const float* Q = (const float*)d_in[0];
    const float* K = (const float*)d_in[1];
    const float* V = (const float*)d_in[2];
    float* O = (float*)d_out;
    float* A = (float*)d_out + (size_t)Bb * Ls * Hh * Ee;   // tuple order: (V, A)

    cudaFuncSetAttribute(attn1, cudaFuncAttributeMaxDynamicSharedMemorySize,
                         SMEM_FLOATS * 4);
    dim3 grid(Ls / BQ / 2, Hh, Bb);   // 8 x 16 x 2 = 256 blocks, 2 row-tiles each
    attn1<<<grid, 256, SMEM_FLOATS * 4>>>(Q, K, V, O, A);
    normA<<<Bb * Hh * Ls, 256>>>(A);
}

// round 4
// speedup vs baseline: 2.0317x; 1.0445x over previous
#include <cuda_runtime.h>
#include <math.h>

#define Bb 2
#define Ls 2048
#define Hh 16
#define Ee 64
#define BQ 128
#define BK 64
#define SCALE_LOG2E (0.125f * 1.4426950408889634f)
#define QW 132
#define KW 68
#define VW 68
#define PW 132
#define SMEM_FLOATS (64*QW + 64*KW + 64*VW + 64*PW)   // 25600 floats = 100 KB

__device__ float g_Zinv[Bb * Hh * Ls];

// Q/K/V layout: [B, L, H, E] -> ((b*L + l)*H + h)*E + e   (row stride H*E = 1024)
// A layout:     [B, H, L, S]
// O layout:     [B, L, H, E]

__global__ __launch_bounds__(256, 2)
void attn1(const float* __restrict__ Q, const float* __restrict__ K,
           const float* __restrict__ V, float* __restrict__ O,
           float* __restrict__ A)
{
    extern __shared__ float sm[];
    float* QsT = sm;                       // [64][QW]  Q^T, scale folded
    float* Ks  = sm + 64 * QW;             // [64][KW]  K^T tile
    float* Vs  = Ks + 64 * KW;             // [64][VW]  V tile row-major
    float* PT  = Vs + 64 * VW;             // [64][PW]  P~^T tile

    const int h   = blockIdx.y;
    const int b   = blockIdx.z;
    const int tid = threadIdx.x;
    const int tx  = tid & 15;
    const int ty  = tid >> 4;
    const int bh  = b * Hh + h;

    const float* Kb0 = K + ((size_t)b * Ls * Hh + h) * Ee;
    const float* Vb0 = V + ((size_t)b * Ls * Hh + h) * Ee;

    // two row-tiles per block for load balance: mt and 15-mt (36 K-tiles total)
    #pragma unroll 1
    for (int half = 0; half < 2; half++) {
        const int mt = half ? (Ls / BQ - 1) - blockIdx.x : blockIdx.x;
        const int m0 = mt * BQ;

        const float* Qbase = Q + (((size_t)b * Ls + m0) * Hh + h) * Ee;
        float* Abase       = A + ((size_t)bh * Ls + m0) * (size_t)Ls;

        __syncthreads();   // previous half's smem reads done

        // ---- load Q tile transposed, folding scale*log2(e) ----
        #pragma unroll
        for (int p = 0; p < 8; p++) {
            int r = ty + p * 16;
            float4 v = *(const float4*)(Qbase + (size_t)r * (Hh * Ee) + tx * 4);
            QsT[(tx * 4 + 0) * QW + r] = v.x * SCALE_LOG2E;
            QsT[(tx * 4 + 1) * QW + r] = v.y * SCALE_LOG2E;
            QsT[(tx * 4 + 2) * QW + r] = v.z * SCALE_LOG2E;
            QsT[(tx * 4 + 3) * QW + r] = v.w * SCALE_LOG2E;
        }

        // ---- zero-fill fully masked A columns [m0+BQ, Ls) ----
        if (m0 + BQ < Ls) {
            int c0  = m0 + BQ;
            int w4  = (Ls - c0) >> 2;
            int tot = BQ * w4;
            for (int idx = tid; idx < tot; idx += 256) {
                int r  = idx / w4;
                int c4 = idx - r * w4;
                *(float4*)(Abase + (size_t)r * Ls + c0 + c4 * 4) =
                    make_float4(0.f, 0.f, 0.f, 0.f);
            }
        }

        float oacc[8][4];
        float zp[8];
        #pragma unroll
        for (int i = 0; i < 8; i++) {
            zp[i] = 0.f;
            #pragma unroll
            for (int j = 0; j < 4; j++) oacc[i][j] = 0.f;
        }

        __syncthreads();

        const int ntiles = 2 * mt + 2;
        for (int nt = 0; nt < ntiles; nt++) {
            const int n0 = nt * BK;
            const float* Kbase = Kb0 + (size_t)n0 * (Hh * Ee);
            const float* Vbase = Vb0 + (size_t)n0 * (Hh * Ee);

            // load K (transposed) and V (row-major)
            #pragma unroll
            for (int p = 0; p < 4; p++) {
                int c = ty + p * 16;
                float4 kv = *(const float4*)(Kbase + (size_t)c * (Hh * Ee) + tx * 4);
                Ks[(tx * 4 + 0) * KW + c] = kv.x;
                Ks[(tx * 4 + 1) * KW + c] = kv.y;
                Ks[(tx * 4 + 2) * KW + c] = kv.z;
                Ks[(tx * 4 + 3) * KW + c] = kv.w;
                *(float4*)(Vs + c * VW + tx * 4) =
                    *(const float4*)(Vbase + (size_t)c * (Hh * Ee) + tx * 4);
            }
            __syncthreads();

            // ---- S = Q K^T (scaled, in log2 domain) ----
            float acc[8][4];
            #pragma unroll
            for (int i = 0; i < 8; i++)
                #pragma unroll
                for (int j = 0; j < 4; j++) acc[i][j] = 0.f;

            #pragma unroll 8
            for (int e = 0; e < Ee; e++) {
                float4 a0 = *(const float4*)&QsT[e * QW + ty * 8];
                float4 a1 = *(const float4*)&QsT[e * QW + ty * 8 + 4];
                float4 bv = *(const float4*)&Ks[e * KW + tx * 4];
                float av[8] = {a0.x, a0.y, a0.z, a0.w, a1.x, a1.y, a1.z, a1.w};
                float bb[4] = {bv.x, bv.y, bv.z, bv.w};
                #pragma unroll
                for (int i = 0; i < 8; i++)
                    #pragma unroll
                    for (int j = 0; j < 4; j++)
                        acc[i][j] = fmaf(av[i], bb[j], acc[i][j]);
            }

            // ---- P~ = exp2(S) with causal mask; accumulate Z partials ----
            if (nt >= 2 * mt) {
                #pragma unroll
                for (int i = 0; i < 8; i++)
                    #pragma unroll
                    for (int j = 0; j < 4; j++) {
                        int col = n0 + tx * 4 + j;
                        int row = m0 + ty * 8 + i;
                        acc[i][j] = (col <= row) ? exp2f(acc[i][j]) : 0.f;
                    }
            } else {
                #pragma unroll
                for (int i = 0; i < 8; i++)
                    #pragma unroll
                    for (int j = 0; j < 4; j++)
                        acc[i][j] = exp2f(acc[i][j]);
            }
            #pragma unroll
            for (int i = 0; i < 8; i++)
                zp[i] += (acc[i][0] + acc[i][1]) + (acc[i][2] + acc[i][3]);

            // ---- write unnormalized P~ to A (registers -> global, coalesced) ----
            #pragma unroll
            for (int i = 0; i < 8; i++)
                *(float4*)(Abase + (size_t)(ty * 8 + i) * Ls + n0 + tx * 4) =
                    make_float4(acc[i][0], acc[i][1], acc[i][2], acc[i][3]);

            // ---- stage P~^T into smem for the PV GEMM ----
            #pragma unroll
            for (int j = 0; j < 4; j++) {
                *(float4*)&PT[(tx * 4 + j) * PW + ty * 8] =
                    make_float4(acc[0][j], acc[1][j], acc[2][j], acc[3][j]);
                *(float4*)&PT[(tx * 4 + j) * PW + ty * 8 + 4] =
                    make_float4(acc[4][j], acc[5][j], acc[6][j], acc[7][j]);
            }
            __syncthreads();

            // ---- O += P~ V ----
            #pragma unroll 8
            for (int c = 0; c < BK; c++) {
                float4 p0 = *(const float4*)&PT[c * PW + ty * 8];
                float4 p1 = *(const float4*)&PT[c * PW + ty * 8 + 4];
                float4 vv = *(const float4*)&Vs[c * VW + tx * 4];
                float pv[8] = {p0.x, p0.y, p0.z, p0.w, p1.x, p1.y, p1.z, p1.w};
                float vb[4] = {vv.x, vv.y, vv.z, vv.w};
                #pragma unroll
                for (int i = 0; i < 8; i++)
                    #pragma unroll
                    for (int j = 0; j < 4; j++)
                        oacc[i][j] = fmaf(pv[i], vb[j], oacc[i][j]);
            }
            __syncthreads();
        }

        // ---- finalize: Z reduce, scale O, store O + Zinv ----
        #pragma unroll
        for (int i = 0; i < 8; i++) {
            float z = zp[i];
            #pragma unroll
            for (int o = 8; o >= 1; o >>= 1)
                z += __shfl_xor_sync(0xffffffffu, z, o, 16);
            float zi = 1.0f / z;
            int row = m0 + ty * 8 + i;
            if (tx == 0) g_Zinv[bh * Ls + row] = zi;
            float4 w = make_float4(oacc[i][0] * zi, oacc[i][1] * zi,
                                   oacc[i][2] * zi, oacc[i][3] * zi);
            *(float4*)(O + (((size_t)b * Ls + row) * Hh + h) * Ee + tx * 4) = w;
        }
    }
}

// normalize the lower-triangular region of A by 1/Z
__global__ __launch_bounds__(256)
void normA(float* __restrict__ A)
{
    int row = blockIdx.x;                      // (b*H + h)*L + r
    int r   = row & (Ls - 1);
    int n4  = (((r >> 7) + 1) << 7) >> 2;      // float4 count to scale
    float zi = g_Zinv[row];
    float4* p = (float4*)(A + (size_t)row * Ls);
    for (int i = threadIdx.x; i < n4; i += 256) {
        float4 v = p[i];
        v.x *= zi; v.y *= zi; v.z *= zi; v.w *= zi;
        p[i] = v;
    }
}

extern "C" void kernel_launch(void* const* d_in, const int* in_sizes, int n_in,
                              void* d_out, int out_size) {
    const float* Q = (const float*)d_in[0];
    const float* K = (const float*)d_in[1];
    const float* V = (const float*)d_in[2];
    float* O = (float*)d_out;
    float* A = (float*)d_out + (size_t)Bb * Ls * Hh * Ee;   // tuple order: (V, A)

    cudaFuncSetAttribute(attn1, cudaFuncAttributeMaxDynamicSharedMemorySize,
                         SMEM_FLOATS * 4);
    dim3 grid(Ls / BQ / 2, Hh, Bb);   // 8 x 16 x 2 = 256 blocks, 2 row-tiles each
    attn1<<<grid, 256, SMEM_FLOATS * 4>>>(Q, K, V, O, A);
    normA<<<Bb * Hh * Ls, 256>>>(A);
}

// round 9
// speedup vs baseline: 2.7835x; 1.3700x over previous
#include <cuda_runtime.h>
#include <math.h>

#define Bb 2
#define Ls 2048
#define Hh 16
#define Ee 64
#define BQ 64
#define BK 64
#define SCALE_LOG2E (0.125f * 1.4426950408889634f)
#define PW 72                 // 16-bit smem tile pitch (144B rows: conflict-free ldmatrix)

typedef unsigned int  u32;
typedef unsigned short u16;

__device__ __forceinline__ u32 sm32(const void* p) {
    return (u32)__cvta_generic_to_shared(p);
}
__device__ __forceinline__ void ldsm4(u32& r0, u32& r1, u32& r2, u32& r3, u32 a) {
    asm volatile("ldmatrix.sync.aligned.m8n8.x4.shared.b16 {%0,%1,%2,%3},[%4];"
                 : "=r"(r0), "=r"(r1), "=r"(r2), "=r"(r3) : "r"(a));
}
__device__ __forceinline__ void mma16816(float* d, const u32* a, u32 b0, u32 b1) {
    asm volatile("mma.sync.aligned.m16n8k16.row.col.f32.bf16.bf16.f32 "
                 "{%0,%1,%2,%3},{%4,%5,%6,%7},{%8,%9},{%0,%1,%2,%3};"
                 : "+f"(d[0]), "+f"(d[1]), "+f"(d[2]), "+f"(d[3])
                 : "r"(a[0]), "r"(a[1]), "r"(a[2]), "r"(a[3]), "r"(b0), "r"(b1));
}
// round-to-nearest-even bf16, returned as fp32 bit-pattern with low 16 bits zero
__device__ __forceinline__ u32 bf16_top(float x) {
    u32 u = __float_as_uint(x);
    return (u + 0x7FFFu + ((u >> 16) & 1u)) & 0xFFFF0000u;
}
// split x into hi/lo bf16 (each as 16-bit pattern)
__device__ __forceinline__ void split_ui(float x, u32& h16, u32& l16) {
    u32 hb = bf16_top(x);
    float fl = x - __uint_as_float(hb);
    h16 = hb >> 16;
    l16 = bf16_top(fl) >> 16;
}

// Q/K/V: [B, L, H, E] -> ((b*L + l)*H + h)*E + e   (row stride H*E = 1024)
// A:     [B, H, L, S]
// O:     [B, L, H, E]

__global__ __launch_bounds__(256, 2)
void attn(const float* __restrict__ Q, const float* __restrict__ K,
          const float* __restrict__ V, float* __restrict__ O, float* __restrict__ A)
{
    extern __shared__ char smraw[];
    u16* Qhi = (u16*)smraw;            // [64][PW] Q (scale folded), hi bf16
    u16* Qlo = Qhi + 64 * PW;
    u16* Khi = Qlo + 64 * PW;          // [n][e]
    u16* Klo = Khi + 64 * PW;
    u16* Vhi = Klo + 64 * PW;          // transposed: [e][s]
    u16* Vlo = Vhi + 64 * PW;
    u16* Phi = Vlo + 64 * PW;          // [m][s]
    u16* Plo = Phi + 64 * PW;
    float* Zs = (float*)(Plo + 64 * PW);   // [64]

    const int mt  = (Ls / BQ - 1) - blockIdx.x;    // heavy tiles launch first
    const int h   = blockIdx.y, b = blockIdx.z;
    const int tid = threadIdx.x;
    const int l   = tid & 31, wid = tid >> 5;
    const int wm  = wid >> 2, wn = wid & 3;
    const int m0  = mt * BQ;
    const int bh  = b * Hh + h;

    const float* Qb = Q + (((size_t)b * Ls + m0) * Hh + h) * Ee;
    const float* Kb = K + ((size_t)b * Ls * Hh + h) * Ee;
    const float* Vb = V + ((size_t)b * Ls * Hh + h) * Ee;
    float* Ab = A + ((size_t)bh * Ls + m0) * (size_t)Ls;

    // ---- load Q tile, fold scale, split to bf16 hi/lo ----
    {
        int r = tid >> 4, e = (tid & 15) * 4;
        #pragma unroll
        for (int p = 0; p < 4; p++) {
            int rr = r + 16 * p;
            float4 v = *(const float4*)(Qb + (size_t)rr * (Hh * Ee) + e);
            float xs[4];
            xs[0] = v.x * SCALE_LOG2E; xs[1] = v.y * SCALE_LOG2E;
            xs[2] = v.z * SCALE_LOG2E; xs[3] = v.w * SCALE_LOG2E;
            u32 hh[4], ll[4];
            #pragma unroll
            for (int j = 0; j < 4; j++) split_ui(xs[j], hh[j], ll[j]);
            *(u32*)&Qhi[rr * PW + e]     = hh[0] | (hh[1] << 16);
            *(u32*)&Qhi[rr * PW + e + 2] = hh[2] | (hh[3] << 16);
            *(u32*)&Qlo[rr * PW + e]     = ll[0] | (ll[1] << 16);
            *(u32*)&Qlo[rr * PW + e + 2] = ll[2] | (ll[3] << 16);
        }
    }
    if (tid < 64) Zs[tid] = 0.f;

    // ---- zero-fill fully masked A columns [m0+BQ, Ls) ----
    if (m0 + BQ < Ls) {
        int c0  = m0 + BQ;
        int w4  = (Ls - c0) >> 2;
        int tot = BQ * w4;
        for (int idx = tid; idx < tot; idx += 256) {
            int r  = idx / w4;
            int c4 = idx - r * w4;
            *(float4*)(Ab + (size_t)r * Ls + c0 + c4 * 4) = make_float4(0.f, 0.f, 0.f, 0.f);
        }
    }

    float zp[4];
    zp[0] = zp[1] = zp[2] = zp[3] = 0.f;
    float oacc[2][2][4];
    #pragma unroll
    for (int i = 0; i < 2; i++)
        #pragma unroll
        for (int j = 0; j < 2; j++)
            #pragma unroll
            for (int k = 0; k < 4; k++) oacc[i][j][k] = 0.f;

    const u32 uQhi = sm32(Qhi), uQlo = sm32(Qlo);
    const u32 uKhi = sm32(Khi), uKlo = sm32(Klo);
    const u32 uVhi = sm32(Vhi), uVlo = sm32(Vlo);
    const u32 uPhi = sm32(Phi), uPlo = sm32(Plo);
    // ldmatrix address offsets (bytes)
    const u32 aOff = ((32 * wm + (l & 15)) * PW + 8 * (l >> 4)) * 2;
    const u32 bOff = ((16 * wn + 8 * ((l >> 3) & 1) + (l & 7)) * PW + 8 * (l >> 4)) * 2;

    for (int nt = 0; nt <= mt; nt++) {
        __syncthreads();     // previous iteration's smem consumers done
        // ---- load K (row-major [n][e]) and V (transposed [e][s]), split hi/lo ----
        {
            int r = tid >> 4, e = (tid & 15) * 4;
            #pragma unroll
            for (int p = 0; p < 4; p++) {
                int rr = r + 16 * p;
                float4 kv = *(const float4*)(Kb + (size_t)(nt * BK + rr) * (Hh * Ee) + e);
                u32 hh[4], ll[4];
                split_ui(kv.x, hh[0], ll[0]); split_ui(kv.y, hh[1], ll[1]);
                split_ui(kv.z, hh[2], ll[2]); split_ui(kv.w, hh[3], ll[3]);
                *(u32*)&Khi[rr * PW + e]     = hh[0] | (hh[1] << 16);
                *(u32*)&Khi[rr * PW + e + 2] = hh[2] | (hh[3] << 16);
                *(u32*)&Klo[rr * PW + e]     = ll[0] | (ll[1] << 16);
                *(u32*)&Klo[rr * PW + e + 2] = ll[2] | (ll[3] << 16);

                float4 vv = *(const float4*)(Vb + (size_t)(nt * BK + rr) * (Hh * Ee) + e);
                float vs[4];
                vs[0] = vv.x; vs[1] = vv.y; vs[2] = vv.z; vs[3] = vv.w;
                #pragma unroll
                for (int j = 0; j < 4; j++) {
                    u32 vh, vl;
                    split_ui(vs[j], vh, vl);
                    Vhi[(e + j) * PW + rr] = (u16)vh;
                    Vlo[(e + j) * PW + rr] = (u16)vl;
                }
            }
        }
        __syncthreads();

        // ---- S = Q K^T via bf16x3 mma ----
        float sacc[2][2][4];
        #pragma unroll
        for (int i = 0; i < 2; i++)
            #pragma unroll
            for (int j = 0; j < 2; j++)
                #pragma unroll
                for (int k = 0; k < 4; k++) sacc[i][j][k] = 0.f;

        #pragma unroll
        for (int ks = 0; ks < 4; ks++) {
            u32 ah[2][4], al[2][4], bh4[4], bl4[4];
            ldsm4(ah[0][0], ah[0][1], ah[0][2], ah[0][3], uQhi + aOff + ks * 32);
            ldsm4(ah[1][0], ah[1][1], ah[1][2], ah[1][3], uQhi + aOff + 16 * PW * 2 + ks * 32);
            ldsm4(al[0][0], al[0][1], al[0][2], al[0][3], uQlo + aOff + ks * 32);
            ldsm4(al[1][0], al[1][1], al[1][2], al[1][3], uQlo + aOff + 16 * PW * 2 + ks * 32);
            ldsm4(bh4[0], bh4[1], bh4[2], bh4[3], uKhi + bOff + ks * 32);
            ldsm4(bl4[0], bl4[1], bl4[2], bl4[3], uKlo + bOff + ks * 32);
            #pragma unroll
            for (int am = 0; am < 2; am++)
                #pragma unroll
                for (int an = 0; an < 2; an++) {
                    mma16816(sacc[am][an], ah[am], bh4[an], bh4[an + 2]);   // hi*hi
                    mma16816(sacc[am][an], ah[am], bl4[an], bl4[an + 2]);   // hi*lo
                    mma16816(sacc[am][an], al[am], bh4[an], bh4[an + 2]);   // lo*hi
                }
        }

        // ---- exp2, causal mask, Z partials, A write, P~ -> smem ----
        const int n0 = nt * BK;
        const bool diag = (nt == mt);
        #pragma unroll
        for (int am = 0; am < 2; am++) {
            #pragma unroll
            for (int an = 0; an < 2; an++) {
                float* d = sacc[am][an];
                int rl0 = 32 * wm + 16 * am + (l >> 2);
                int c   = 16 * wn + 8 * an + 2 * (l & 3);
                int gr0 = m0 + rl0, gc = n0 + c;
                float p0 = exp2f(d[0]), p1 = exp2f(d[1]);
                float p2 = exp2f(d[2]), p3 = exp2f(d[3]);
                if (diag) {
                    if (gc     > gr0)     p0 = 0.f;
                    if (gc + 1 > gr0)     p1 = 0.f;
                    if (gc     > gr0 + 8) p2 = 0.f;
                    if (gc + 1 > gr0 + 8) p3 = 0.f;
                }
                zp[2 * am]     += p0 + p1;
                zp[2 * am + 1] += p2 + p3;
                *(float2*)(Ab + (size_t)rl0 * Ls + gc)       = make_float2(p0, p1);
                *(float2*)(Ab + (size_t)(rl0 + 8) * Ls + gc) = make_float2(p2, p3);
                u32 h0, l0v, h1, l1v;
                split_ui(p0, h0, l0v); split_ui(p1, h1, l1v);
                *(u32*)&Phi[rl0 * PW + c] = h0 | (h1 << 16);
                *(u32*)&Plo[rl0 * PW + c] = l0v | (l1v << 16);
                split_ui(p2, h0, l0v); split_ui(p3, h1, l1v);
                *(u32*)&Phi[(rl0 + 8) * PW + c] = h0 | (h1 << 16);
                *(u32*)&Plo[(rl0 + 8) * PW + c] = l0v | (l1v << 16);
            }
        }
        __syncthreads();

        // ---- O += P~ V via bf16x3 mma ----
        #pragma unroll
        for (int ks = 0; ks < 4; ks++) {
            u32 ah[2][4], al[2][4], bh4[4], bl4[4];
            ldsm4(ah[0][0], ah[0][1], ah[0][2], ah[0][3], uPhi + aOff + ks * 32);
            ldsm4(ah[1][0], ah[1][1], ah[1][2], ah[1][3], uPhi + aOff + 16 * PW * 2 + ks * 32);
            ldsm4(al[0][0], al[0][1], al[0][2], al[0][3], uPlo + aOff + ks * 32);
            ldsm4(al[1][0], al[1][1], al[1][2], al[1][3], uPlo + aOff + 16 * PW * 2 + ks * 32);
            ldsm4(bh4[0], bh4[1], bh4[2], bh4[3], uVhi + bOff + ks * 32);
            ldsm4(bl4[0], bl4[1], bl4[2], bl4[3], uVlo + bOff + ks * 32);
            #pragma unroll
            for (int am = 0; am < 2; am++)
                #pragma unroll
                for (int an = 0; an < 2; an++) {
                    mma16816(oacc[am][an], ah[am], bh4[an], bh4[an + 2]);
                    mma16816(oacc[am][an], ah[am], bl4[an], bl4[an + 2]);
                    mma16816(oacc[am][an], al[am], bh4[an], bh4[an + 2]);
                }
        }
    }

    // ---- Z reduction: quad shfl + smem atomics ----
    #pragma unroll
    for (int i = 0; i < 4; i++) {
        float z = zp[i];
        z += __shfl_xor_sync(0xffffffffu, z, 1);
        z += __shfl_xor_sync(0xffffffffu, z, 2);
        if ((l & 3) == 0) {
            int rl = 32 * wm + 16 * (i >> 1) + (l >> 2) + 8 * (i & 1);
            atomicAdd(&Zs[rl], z);
        }
    }
    __syncthreads();
    if (tid < 64) Zs[tid] = 1.0f / Zs[tid];
    __syncthreads();

    // ---- O epilogue (scaled by 1/Z) ----
    #pragma unroll
    for (int am = 0; am < 2; am++) {
        int rl0 = 32 * wm + 16 * am + (l >> 2);
        float zi0 = Zs[rl0], zi1 = Zs[rl0 + 8];
        int gr0 = m0 + rl0;
        #pragma unroll
        for (int an = 0; an < 2; an++) {
            float* d = oacc[am][an];
            int e = 16 * wn + 8 * an + 2 * (l & 3);
            *(float2*)(O + (((size_t)b * Ls + gr0) * Hh + h) * Ee + e) =
                make_float2(d[0] * zi0, d[1] * zi0);
            *(float2*)(O + (((size_t)b * Ls + gr0 + 8) * Hh + h) * Ee + e) =
                make_float2(d[2] * zi1, d[3] * zi1);
        }
    }

    // ---- fused A normalization (this block's rows, lower-triangular span) ----
    {
        int w4 = (mt + 1) * 16;   // float4s per row
        for (int r = wid; r < 64; r += 8) {
            float zi = Zs[r];
            float4* row = (float4*)(Ab + (size_t)r * Ls);
            for (int c4 = l; c4 < w4; c4 += 32) {
                float4 v = row[c4];
                v.x *= zi; v.y *= zi; v.z *= zi; v.w *= zi;
                row[c4] = v;
            }
        }
    }
}

extern "C" void kernel_launch(void* const* d_in, const int* in_sizes, int n_in,
                              void* d_out, int out_size) {
    const float* Q = (const float*)d_in[0];
    const float* K = (const float*)d_in[1];
    const float* V = (const float*)d_in[2];
    float* O = (float*)d_out;
    float* A = (float*)d_out + (size_t)Bb * Ls * Hh * Ee;   // tuple order: (V, A)

    int smem = (8 * 64 * PW) * 2 + 64 * 4;   // 8 x 16-bit tiles + Zs
    cudaFuncSetAttribute(attn, cudaFuncAttributeMaxDynamicSharedMemorySize, smem);
    dim3 grid(Ls / BQ, Hh, Bb);   // 32 x 16 x 2 = 1024 blocks, heavy-first
    attn<<<grid, 256, smem>>>(Q, K, V, O, A);
}

// round 13
// speedup vs baseline: 4.1372x; 1.4863x over previous
#include <cuda_runtime.h>
#include <math.h>

#define Bb 2
#define Ls 2048
#define Hh 16
#define Ee 64
#define BQ 64
#define BK 64
#define SCALE_LOG2E (0.125f * 1.4426950408889634f)
#define PW 72                 // 16-bit smem tile pitch (144B rows: conflict-free ldmatrix)

typedef unsigned int  u32;
typedef unsigned short u16;

__device__ __forceinline__ u32 sm32(const void* p) {
    return (u32)__cvta_generic_to_shared(p);
}
__device__ __forceinline__ void ldsm4(u32& r0, u32& r1, u32& r2, u32& r3, u32 a) {
    asm volatile("ldmatrix.sync.aligned.m8n8.x4.shared.b16 {%0,%1,%2,%3},[%4];"
                 : "=r"(r0), "=r"(r1), "=r"(r2), "=r"(r3) : "r"(a));
}
__device__ __forceinline__ void ldsm4t(u32& r0, u32& r1, u32& r2, u32& r3, u32 a) {
    asm volatile("ldmatrix.sync.aligned.m8n8.x4.trans.shared.b16 {%0,%1,%2,%3},[%4];"
                 : "=r"(r0), "=r"(r1), "=r"(r2), "=r"(r3) : "r"(a));
}
__device__ __forceinline__ void mma16816(float* d, const u32* a, u32 b0, u32 b1) {
    asm volatile("mma.sync.aligned.m16n8k16.row.col.f32.f16.f16.f32 "
                 "{%0,%1,%2,%3},{%4,%5,%6,%7},{%8,%9},{%0,%1,%2,%3};"
                 : "+f"(d[0]), "+f"(d[1]), "+f"(d[2]), "+f"(d[3])
                 : "r"(a[0]), "r"(a[1]), "r"(a[2]), "r"(a[3]), "r"(b0), "r"(b1));
}
// fp32 -> fp16 round-trip (value rounded to nearest fp16, returned as fp32)
__device__ __forceinline__ float half_rt(float x) {
    float y;
    asm("{\n\t.reg .b16 h;\n\tcvt.rn.f16.f32 h, %1;\n\tcvt.f32.f16 %0, h;\n\t}"
        : "=f"(y) : "f"(x));
    return y;
}
// pack two floats as fp16x2: lo -> low half, hi -> high half
__device__ __forceinline__ u32 f16x2(float lo, float hi) {
    u32 r;
    asm("cvt.rn.f16x2.f32 %0, %1, %2;" : "=r"(r) : "f"(hi), "f"(lo));
    return r;
}
__device__ __forceinline__ float ex2(float x) {
    float y;
    asm("ex2.approx.f32 %0, %1;" : "=f"(y) : "f"(x));
    return y;
}

// Q/K/V: [B, L, H, E] -> ((b*L + l)*H + h)*E + e   (row stride H*E = 1024)
// A:     [B, H, L, S]
// O:     [B, L, H, E]

__global__ __launch_bounds__(256, 2)
void attn(const float* __restrict__ Q, const float* __restrict__ K,
          const float* __restrict__ V, float* __restrict__ O, float* __restrict__ A)
{
    extern __shared__ char smraw[];
    u16* Qhi = (u16*)smraw;            // [64][PW] Q (scale folded), hi fp16
    u16* Qlo = Qhi + 64 * PW;
    u16* Khi = Qlo + 64 * PW;          // [n][e]
    u16* Klo = Khi + 64 * PW;
    u16* Vhi = Klo + 64 * PW;          // row-major [s][e] (trans-loaded for PV)
    u16* Vlo = Vhi + 64 * PW;
    u16* Phi = Vlo + 64 * PW;          // [m][s], fp16 only (2-term PV)
    float* Zs = (float*)(Phi + 64 * PW);   // [64]

    const int mt  = (Ls / BQ - 1) - blockIdx.x;    // heavy tiles launch first
    const int h   = blockIdx.y, b = blockIdx.z;
    const int tid = threadIdx.x;
    const int l   = tid & 31, wid = tid >> 5;
    const int wm  = wid >> 2, wn = wid & 3;
    const int m0  = mt * BQ;
    const int bh  = b * Hh + h;

    const float* Qb = Q + (((size_t)b * Ls + m0) * Hh + h) * Ee;
    const float* Kb = K + ((size_t)b * Ls * Hh + h) * Ee;
    const float* Vb = V + ((size_t)b * Ls * Hh + h) * Ee;
    float* Ab = A + ((size_t)bh * Ls + m0) * (size_t)Ls;

    // ---- load Q tile, fold scale, split to fp16 hi/lo ----
    {
        int r = tid >> 4, e = (tid & 15) * 4;
        #pragma unroll
        for (int p = 0; p < 4; p++) {
            int rr = r + 16 * p;
            float4 v = *(const float4*)(Qb + (size_t)rr * (Hh * Ee) + e);
            float xs[4];
            xs[0] = v.x * SCALE_LOG2E; xs[1] = v.y * SCALE_LOG2E;
            xs[2] = v.z * SCALE_LOG2E; xs[3] = v.w * SCALE_LOG2E;
            float hf[4], lf[4];
            #pragma unroll
            for (int j = 0; j < 4; j++) { hf[j] = half_rt(xs[j]); lf[j] = xs[j] - hf[j]; }
            *(u32*)&Qhi[rr * PW + e]     = f16x2(hf[0], hf[1]);
            *(u32*)&Qhi[rr * PW + e + 2] = f16x2(hf[2], hf[3]);
            *(u32*)&Qlo[rr * PW + e]     = f16x2(lf[0], lf[1]);
            *(u32*)&Qlo[rr * PW + e + 2] = f16x2(lf[2], lf[3]);
        }
    }
    if (tid < 64) Zs[tid] = 0.f;

    // ---- zero-fill fully masked A columns [m0+BQ, Ls) ----
    if (m0 + BQ < Ls) {
        int c0  = m0 + BQ;
        int w4  = (Ls - c0) >> 2;
        int tot = BQ * w4;
        for (int idx = tid; idx < tot; idx += 256) {
            int r  = idx / w4;
            int c4 = idx - r * w4;
            *(float4*)(Ab + (size_t)r * Ls + c0 + c4 * 4) = make_float4(0.f, 0.f, 0.f, 0.f);
        }
    }

    float zp[4];
    zp[0] = zp[1] = zp[2] = zp[3] = 0.f;
    float oacc[2][2][4];
    #pragma unroll
    for (int i = 0; i < 2; i++)
        #pragma unroll
        for (int j = 0; j < 2; j++)
            #pragma unroll
            for (int k = 0; k < 4; k++) oacc[i][j][k] = 0.f;

    const u32 uQhi = sm32(Qhi), uQlo = sm32(Qlo);
    const u32 uKhi = sm32(Khi), uKlo = sm32(Klo);
    const u32 uVhi = sm32(Vhi), uVlo = sm32(Vlo);
    const u32 uPhi = sm32(Phi);
    // ldmatrix address offsets (bytes)
    const u32 aOff = ((32 * wm + (l & 15)) * PW + 8 * (l >> 4)) * 2;
    const u32 bOff = ((16 * wn + 8 * ((l >> 3) & 1) + (l & 7)) * PW + 8 * (l >> 4)) * 2;
    // trans-B offset for V ([s][e] rows; mats: (e-grp0,s-lo)(e-grp1,s-lo)(e-grp0,s-hi)(e-grp1,s-hi))
    const u32 vOff = (((l & 7) + 8 * (l >> 4)) * PW + 16 * wn + 8 * ((l >> 3) & 1)) * 2;

    for (int nt = 0; nt <= mt; nt++) {
        __syncthreads();     // previous iteration's smem consumers done
        // ---- load K ([n][e]) and V ([s][e], row-major), split to fp16 hi/lo ----
        {
            int r = tid >> 4, e = (tid & 15) * 4;
            #pragma unroll
            for (int p = 0; p < 4; p++) {
                int rr = r + 16 * p;
                float4 kv = *(const float4*)(Kb + (size_t)(nt * BK + rr) * (Hh * Ee) + e);
                float kh[4], kl[4];
                kh[0] = half_rt(kv.x); kl[0] = kv.x - kh[0];
                kh[1] = half_rt(kv.y); kl[1] = kv.y - kh[1];
                kh[2] = half_rt(kv.z); kl[2] = kv.z - kh[2];
                kh[3] = half_rt(kv.w); kl[3] = kv.w - kh[3];
                *(u32*)&Khi[rr * PW + e]     = f16x2(kh[0], kh[1]);
                *(u32*)&Khi[rr * PW + e + 2] = f16x2(kh[2], kh[3]);
                *(u32*)&Klo[rr * PW + e]     = f16x2(kl[0], kl[1]);
                *(u32*)&Klo[rr * PW + e + 2] = f16x2(kl[2], kl[3]);

                float4 vv = *(const float4*)(Vb + (size_t)(nt * BK + rr) * (Hh * Ee) + e);
                float vh[4], vl[4];
                vh[0] = half_rt(vv.x); vl[0] = vv.x - vh[0];
                vh[1] = half_rt(vv.y); vl[1] = vv.y - vh[1];
                vh[2] = half_rt(vv.z); vl[2] = vv.z - vh[2];
                vh[3] = half_rt(vv.w); vl[3] = vv.w - vh[3];
                *(u32*)&Vhi[rr * PW + e]     = f16x2(vh[0], vh[1]);
                *(u32*)&Vhi[rr * PW + e + 2] = f16x2(vh[2], vh[3]);
                *(u32*)&Vlo[rr * PW + e]     = f16x2(vl[0], vl[1]);
                *(u32*)&Vlo[rr * PW + e + 2] = f16x2(vl[2], vl[3]);
            }
        }
        __syncthreads();

        // ---- S = Q K^T via fp16x3 mma ----
        float sacc[2][2][4];
        #pragma unroll
        for (int i = 0; i < 2; i++)
            #pragma unroll
            for (int j = 0; j < 2; j++)
                #pragma unroll
                for (int k = 0; k < 4; k++) sacc[i][j][k] = 0.f;

        #pragma unroll
        for (int ks = 0; ks < 4; ks++) {
            u32 ah[2][4], al[2][4], bh4[4], bl4[4];
            ldsm4(ah[0][0], ah[0][1], ah[0][2], ah[0][3], uQhi + aOff + ks * 32);
            ldsm4(ah[1][0], ah[1][1], ah[1][2], ah[1][3], uQhi + aOff + 16 * PW * 2 + ks * 32);
            ldsm4(al[0][0], al[0][1], al[0][2], al[0][3], uQlo + aOff + ks * 32);
            ldsm4(al[1][0], al[1][1], al[1][2], al[1][3], uQlo + aOff + 16 * PW * 2 + ks * 32);
            ldsm4(bh4[0], bh4[1], bh4[2], bh4[3], uKhi + bOff + ks * 32);
            ldsm4(bl4[0], bl4[1], bl4[2], bl4[3], uKlo + bOff + ks * 32);
            #pragma unroll
            for (int am = 0; am < 2; am++)
                #pragma unroll
                for (int an = 0; an < 2; an++) {
                    mma16816(sacc[am][an], ah[am], bh4[an], bh4[an + 2]);   // hi*hi
                    mma16816(sacc[am][an], ah[am], bl4[an], bl4[an + 2]);   // hi*lo
                    mma16816(sacc[am][an], al[am], bh4[an], bh4[an + 2]);   // lo*hi
                }
        }

        // ---- exp2, causal mask, Z partials, A write, P (fp16) -> smem ----
        const int n0 = nt * BK;
        const bool diag = (nt == mt);
        #pragma unroll
        for (int am = 0; am < 2; am++) {
            #pragma unroll
            for (int an = 0; an < 2; an++) {
                float* d = sacc[am][an];
                int rl0 = 32 * wm + 16 * am + (l >> 2);
                int c   = 16 * wn + 8 * an + 2 * (l & 3);
                int gr0 = m0 + rl0, gc = n0 + c;
                float p0 = ex2(d[0]), p1 = ex2(d[1]);
                float p2 = ex2(d[2]), p3 = ex2(d[3]);
                if (diag) {
                    if (gc     > gr0)     p0 = 0.f;
                    if (gc + 1 > gr0)     p1 = 0.f;
                    if (gc     > gr0 + 8) p2 = 0.f;
                    if (gc + 1 > gr0 + 8) p3 = 0.f;
                }
                zp[2 * am]     += p0 + p1;
                zp[2 * am + 1] += p2 + p3;
                *(float2*)(Ab + (size_t)rl0 * Ls + gc)       = make_float2(p0, p1);
                *(float2*)(Ab + (size_t)(rl0 + 8) * Ls + gc) = make_float2(p2, p3);
                *(u32*)&Phi[rl0 * PW + c]       = f16x2(p0, p1);
                *(u32*)&Phi[(rl0 + 8) * PW + c] = f16x2(p2, p3);
            }
        }
        __syncthreads();

        // ---- O += P V via fp16 2-term mma (P_hi * (V_hi + V_lo)) ----
        #pragma unroll
        for (int ks = 0; ks < 4; ks++) {
            u32 ah[2][4], bh4[4], bl4[4];
            ldsm4(ah[0][0], ah[0][1], ah[0][2], ah[0][3], uPhi + aOff + ks * 32);
            ldsm4(ah[1][0], ah[1][1], ah[1][2], ah[1][3], uPhi + aOff + 16 * PW * 2 + ks * 32);
            ldsm4t(bh4[0], bh4[1], bh4[2], bh4[3], uVhi + vOff + ks * 16 * PW * 2);
            ldsm4t(bl4[0], bl4[1], bl4[2], bl4[3], uVlo + vOff + ks * 16 * PW * 2);
            #pragma unroll
            for (int am = 0; am < 2; am++)
                #pragma unroll
                for (int an = 0; an < 2; an++) {
                    mma16816(oacc[am][an], ah[am], bh4[an], bh4[an + 2]);
                    mma16816(oacc[am][an], ah[am], bl4[an], bl4[an + 2]);
                }
        }
    }

    // ---- Z reduction: quad shfl + smem atomics ----
    #pragma unroll
    for (int i = 0; i < 4; i++) {
        float z = zp[i];
        z += __shfl_xor_sync(0xffffffffu, z, 1);
        z += __shfl_xor_sync(0xffffffffu, z, 2);
        if ((l & 3) == 0) {
            int rl = 32 * wm + 16 * (i >> 1) + (l >> 2) + 8 * (i & 1);
            atomicAdd(&Zs[rl], z);
        }
    }
    __syncthreads();
    if (tid < 64) Zs[tid] = 1.0f / Zs[tid];
    __syncthreads();

    // ---- O epilogue (scaled by 1/Z) ----
    #pragma unroll
    for (int am = 0; am < 2; am++) {
        int rl0 = 32 * wm + 16 * am + (l >> 2);
        float zi0 = Zs[rl0], zi1 = Zs[rl0 + 8];
        int gr0 = m0 + rl0;
        #pragma unroll
        for (int an = 0; an < 2; an++) {
            float* d = oacc[am][an];
            int e = 16 * wn + 8 * an + 2 * (l & 3);
            *(float2*)(O + (((size_t)b * Ls + gr0) * Hh + h) * Ee + e) =
                make_float2(d[0] * zi0, d[1] * zi0);
            *(float2*)(O + (((size_t)b * Ls + gr0 + 8) * Hh + h) * Ee + e) =
                make_float2(d[2] * zi1, d[3] * zi1);
        }
    }

    // ---- fused A normalization (this block's rows, lower-triangular span) ----
    {
        int w4 = (mt + 1) * 16;   // float4s per row
        for (int r = wid; r < 64; r += 8) {
            float zi = Zs[r];
            float4* row = (float4*)(Ab + (size_t)r * Ls);
            for (int c4 = l; c4 < w4; c4 += 32) {
                float4 v = row[c4];
                v.x *= zi; v.y *= zi; v.z *= zi; v.w *= zi;
                row[c4] = v;
            }
        }
    }
}

extern "C" void kernel_launch(void* const* d_in, const int* in_sizes, int n_in,
                              void* d_out, int out_size) {
    const float* Q = (const float*)d_in[0];
    const float* K = (const float*)d_in[1];
    const float* V = (const float*)d_in[2];
    float* O = (float*)d_out;
    float* A = (float*)d_out + (size_t)Bb * Ls * Hh * Ee;   // tuple order: (V, A)

    int smem = (7 * 64 * PW) * 2 + 64 * 4;   // 7 x 16-bit tiles + Zs
    cudaFuncSetAttribute(attn, cudaFuncAttributeMaxDynamicSharedMemorySize, smem);
    dim3 grid(Ls / BQ, Hh, Bb);   // 32 x 16 x 2 = 1024 blocks, heavy-first
    attn<<<grid, 256, smem>>>(Q, K, V, O, A);
}